// round 4
// baseline (speedup 1.0000x reference)
#include <cuda_runtime.h>

// ---------------------------------------------------------------------------
// MVGeometricBilinear: PGA G(3,0,1) geometric product + equivariant join.
//   out[..., 0:16]  = x * y          (geometric product, e0^2 = 0)
//   out[..., 16:32] = ref_e0123 * dual(dual(x) ^ dual(y))
//
// All Cayley-table signs are computed at COMPILE TIME from blade bitmasks;
// the 16x16 loops fully unroll into ~273 FFMAs of straight-line code.
// Memory-bound: ~144MB DRAM traffic total.
// ---------------------------------------------------------------------------

// Basis order (grade-sorted, matching the reference):
// 0:1  1:e0 2:e1 3:e2 4:e3  5:e01 6:e02 7:e03 8:e12 9:e13 10:e23
// 11:e012 12:e013 13:e023 14:e123 15:e0123
__host__ __device__ constexpr int maskOf(int i) {
    // index -> bitmask of basis vectors {e0=1, e1=2, e2=4, e3=8}
    constexpr int m[16] = {0, 1, 2, 4, 8, 3, 5, 9, 6, 10, 12, 7, 11, 13, 14, 15};
    return m[i];
}
__host__ __device__ constexpr int idxOfMask(int m) {
    constexpr int t[16] = {0, 1, 2, 5, 3, 6, 8, 11, 4, 7, 9, 12, 10, 13, 14, 15};
    return t[m];
}
// Sign from sorting the concatenation (a ascending)(b ascending):
// for each generator j in b, count generators i>j in a.
__host__ __device__ constexpr int reorderSign(int a, int b) {
    int s = 0;
    for (int j = 0; j < 4; j++)
        if (b & (1 << j))
            for (int i = j + 1; i < 4; i++)
                if (a & (1 << i)) s++;
    return (s & 1) ? -1 : 1;
}
// Geometric product term sign: metric e0^2=0 kills any shared e0;
// shared e1/e2/e3 square to +1.
__host__ __device__ constexpr int gpSign(int i, int j) {
    const int a = maskOf(i), b = maskOf(j);
    if (a & b & 1) return 0;              // e0 appears in both -> vanishes
    return reorderSign(a, b);
}
__host__ __device__ constexpr int gpIdx(int i, int j) {
    return idxOfMask(maskOf(i) ^ maskOf(j));
}
// Right complement (dual): cIdx = index of complement blade,
// cSign(i) = sign s with e_i * e_comp(i) = s * e0123 (Euclidean).
__host__ __device__ constexpr int cIdx(int i) { return idxOfMask(15 ^ maskOf(i)); }
__host__ __device__ constexpr int cSign(int i) { return reorderSign(maskOf(i), 15 ^ maskOf(i)); }
// Fused join table: dual(dual(x) ^ dual(y)) expressed directly on x,y.
// dual(x)[p] = cSign(cIdx(p)) * x[cIdx(p)]  =>  dx[cIdx(q)] = cSign(q)*x[q].
// Term (i,j): a = mask(cIdx(i)), b = mask(cIdx(j)); requires a,b disjoint.
// wedge target m = idxOfMask(a|b); output index k = cIdx(m);
// sign = reorderSign(a,b) * cSign(i) * cSign(j) * cSign(m).
__host__ __device__ constexpr int jSign(int i, int j) {
    const int a = maskOf(cIdx(i)), b = maskOf(cIdx(j));
    if (a & b) return 0;
    const int m = idxOfMask(a | b);
    return reorderSign(a, b) * cSign(i) * cSign(j) * cSign(m);
}
__host__ __device__ constexpr int jIdx(int i, int j) {
    const int a = maskOf(cIdx(i)), b = maskOf(cIdx(j));
    if (a & b) return 0;                  // dummy (sign is 0)
    return cIdx(idxOfMask(a | b));
}

__global__ void MVGeometricBilinear_41274635715139_kernel(
    const float4* __restrict__ X,   // (n, 16) as (n, 4) float4
    const float4* __restrict__ Y,
    const float4* __restrict__ R,
    float4* __restrict__ O,         // (n, 32) as (n, 8) float4
    int n)
{
    const int t = blockIdx.x * blockDim.x + threadIdx.x;
    if (t >= n) return;

    float x[16], y[16];
#pragma unroll
    for (int q = 0; q < 4; q++) {
        const float4 v = X[t * 4 + q];
        x[4 * q + 0] = v.x; x[4 * q + 1] = v.y; x[4 * q + 2] = v.z; x[4 * q + 3] = v.w;
    }
#pragma unroll
    for (int q = 0; q < 4; q++) {
        const float4 v = Y[t * 4 + q];
        y[4 * q + 0] = v.x; y[4 * q + 1] = v.y; y[4 * q + 2] = v.z; y[4 * q + 3] = v.w;
    }
    // ref pseudoscalar component (element 15 of the row = .w of 4th float4)
    const float r = R[t * 4 + 3].w;

    float gp[16], jn[16];
#pragma unroll
    for (int k = 0; k < 16; k++) { gp[k] = 0.0f; jn[k] = 0.0f; }

#pragma unroll
    for (int i = 0; i < 16; i++) {
#pragma unroll
        for (int j = 0; j < 16; j++) {
            {   // geometric product term (sign folds into FFMA neg modifier)
                const int s = gpSign(i, j);
                const int k = gpIdx(i, j);
                if (s == 1)       gp[k] += x[i] * y[j];
                else if (s == -1) gp[k] -= x[i] * y[j];
            }
            {   // fused join term
                const int s = jSign(i, j);
                const int k = jIdx(i, j);
                if (s == 1)       jn[k] += x[i] * y[j];
                else if (s == -1) jn[k] -= x[i] * y[j];
            }
        }
    }

    float4* o = O + t * 8;
#pragma unroll
    for (int q = 0; q < 4; q++)
        o[q] = make_float4(gp[4 * q], gp[4 * q + 1], gp[4 * q + 2], gp[4 * q + 3]);
#pragma unroll
    for (int q = 0; q < 4; q++)
        o[4 + q] = make_float4(r * jn[4 * q], r * jn[4 * q + 1],
                               r * jn[4 * q + 2], r * jn[4 * q + 3]);
}

extern "C" void kernel_launch(void* const* d_in, const int* in_sizes, int n_in,
                              void* d_out, int out_size)
{
    const float4* x = (const float4*)d_in[0];
    const float4* y = (const float4*)d_in[1];
    const float4* r = (const float4*)d_in[2];
    float4* o = (float4*)d_out;

    const int n = in_sizes[0] / 16;   // number of multivector points (B*T)
    const int threads = 256;
    const int blocks = (n + threads - 1) / threads;
    MVGeometricBilinear_41274635715139_kernel<<<blocks, threads>>>(x, y, r, o, n);
}

// round 5
// speedup vs baseline: 1.2062x; 1.2062x over previous
#include <cuda_runtime.h>

// ---------------------------------------------------------------------------
// MVGeometricBilinear: PGA G(3,0,1) geometric product + equivariant join.
//   out[..., 0:16]  = x * y          (geometric product, e0^2 = 0)
//   out[..., 16:32] = ref_e0123 * dual(dual(x) ^ dual(y))
//
// Compute core identical to the validated round-3 kernel (compile-time Cayley
// signs, straight-line FFMA). New: shared-memory transposed staging so ALL
// global accesses are fully coalesced (L1 was the bottleneck at 70.9% with
// 4x wavefront inflation from 64B-strided AoS accesses).
// ---------------------------------------------------------------------------

// Basis order (grade-sorted, matching the reference):
// 0:1  1:e0 2:e1 3:e2 4:e3  5:e01 6:e02 7:e03 8:e12 9:e13 10:e23
// 11:e012 12:e013 13:e023 14:e123 15:e0123
__host__ __device__ constexpr int maskOf(int i) {
    constexpr int m[16] = {0, 1, 2, 4, 8, 3, 5, 9, 6, 10, 12, 7, 11, 13, 14, 15};
    return m[i];
}
__host__ __device__ constexpr int idxOfMask(int m) {
    constexpr int t[16] = {0, 1, 2, 5, 3, 6, 8, 11, 4, 7, 9, 12, 10, 13, 14, 15};
    return t[m];
}
__host__ __device__ constexpr int reorderSign(int a, int b) {
    int s = 0;
    for (int j = 0; j < 4; j++)
        if (b & (1 << j))
            for (int i = j + 1; i < 4; i++)
                if (a & (1 << i)) s++;
    return (s & 1) ? -1 : 1;
}
__host__ __device__ constexpr int gpSign(int i, int j) {
    const int a = maskOf(i), b = maskOf(j);
    if (a & b & 1) return 0;              // shared degenerate e0 -> vanishes
    return reorderSign(a, b);
}
__host__ __device__ constexpr int gpIdx(int i, int j) {
    return idxOfMask(maskOf(i) ^ maskOf(j));
}
__host__ __device__ constexpr int cIdx(int i) { return idxOfMask(15 ^ maskOf(i)); }
__host__ __device__ constexpr int cSign(int i) { return reorderSign(maskOf(i), 15 ^ maskOf(i)); }
__host__ __device__ constexpr int jSign(int i, int j) {
    const int a = maskOf(cIdx(i)), b = maskOf(cIdx(j));
    if (a & b) return 0;
    const int m = idxOfMask(a | b);
    return reorderSign(a, b) * cSign(i) * cSign(j) * cSign(m);
}
__host__ __device__ constexpr int jIdx(int i, int j) {
    const int a = maskOf(cIdx(i)), b = maskOf(cIdx(j));
    if (a & b) return 0;
    return cIdx(idxOfMask(a | b));
}

// ---------------------------------------------------------------------------

constexpr int TPB = 256;   // threads per block == points per block
constexpr int SXW = 20;    // smem stride (floats) per point for inputs (16 + 4 pad)
constexpr int SOW = 36;    // smem stride (floats) per point for outputs (32 + 4 pad)

// Shared compute core: 16x16 compile-time-signed bilinear.
__device__ __forceinline__ void mv_compute(const float x[16], const float y[16],
                                           float r, float gp[16], float jn[16])
{
#pragma unroll
    for (int k = 0; k < 16; k++) { gp[k] = 0.0f; jn[k] = 0.0f; }
#pragma unroll
    for (int i = 0; i < 16; i++) {
#pragma unroll
        for (int j = 0; j < 16; j++) {
            {
                const int s = gpSign(i, j);
                const int k = gpIdx(i, j);
                if (s == 1)       gp[k] += x[i] * y[j];
                else if (s == -1) gp[k] -= x[i] * y[j];
            }
            {
                const int s = jSign(i, j);
                const int k = jIdx(i, j);
                if (s == 1)       jn[k] += x[i] * y[j];
                else if (s == -1) jn[k] -= x[i] * y[j];
            }
        }
    }
#pragma unroll
    for (int k = 0; k < 16; k++) jn[k] *= r;
}

__global__ __launch_bounds__(TPB)
void MVGeometricBilinear_41274635715139_kernel(
    const float4* __restrict__ X,   // (n,16) floats = (n,4) float4
    const float4* __restrict__ Y,
    const float*  __restrict__ Rf,  // (n,16) floats; only element 15 used
    float4*       __restrict__ O)   // (n,32) floats = (n,8) float4
{
    __shared__ float sb[TPB * SXW * 2];         // 40 KB
    float* sx = sb;
    float* sy = sb + TPB * SXW;
    float* so = sb;                             // reused after sync (36 KB)

    const int tid  = threadIdx.x;
    const int base = blockIdx.x * TPB;          // first point of this block

    // ref pseudoscalar component; issue early to overlap.
    const float r = Rf[(base + tid) * 16 + 15];

    // --- Stage x, y: fully coalesced LDG.128, padded smem layout ----------
#pragma unroll
    for (int it = 0; it < 4; ++it) {
        const int g = tid + it * TPB;           // float4 index in block tile
        const int p = g >> 2, q = g & 3;
        reinterpret_cast<float4*>(sx + p * SXW + q * 4)[0] = X[base * 4 + g];
        reinterpret_cast<float4*>(sy + p * SXW + q * 4)[0] = Y[base * 4 + g];
    }
    __syncthreads();

    // --- Conflict-free per-thread reads ------------------------------------
    float x[16], y[16];
#pragma unroll
    for (int q = 0; q < 4; ++q) {
        const float4 v = reinterpret_cast<const float4*>(sx + tid * SXW + q * 4)[0];
        x[4 * q + 0] = v.x; x[4 * q + 1] = v.y; x[4 * q + 2] = v.z; x[4 * q + 3] = v.w;
    }
#pragma unroll
    for (int q = 0; q < 4; ++q) {
        const float4 v = reinterpret_cast<const float4*>(sy + tid * SXW + q * 4)[0];
        y[4 * q + 0] = v.x; y[4 * q + 1] = v.y; y[4 * q + 2] = v.z; y[4 * q + 3] = v.w;
    }
    __syncthreads();                            // before buffer reuse as output

    // --- Compute -----------------------------------------------------------
    float gp[16], jn[16];
    mv_compute(x, y, r, gp, jn);

    // --- Stage results (conflict-free STS.128, stride 36) ------------------
#pragma unroll
    for (int q = 0; q < 4; ++q)
        reinterpret_cast<float4*>(so + tid * SOW + q * 4)[0] =
            make_float4(gp[4 * q], gp[4 * q + 1], gp[4 * q + 2], gp[4 * q + 3]);
#pragma unroll
    for (int q = 0; q < 4; ++q)
        reinterpret_cast<float4*>(so + tid * SOW + 16 + q * 4)[0] =
            make_float4(jn[4 * q], jn[4 * q + 1], jn[4 * q + 2], jn[4 * q + 3]);
    __syncthreads();

    // --- Fully coalesced STG.128 writeout ----------------------------------
#pragma unroll
    for (int it = 0; it < 8; ++it) {
        const int g = tid + it * TPB;           // float4 index in out tile
        const int p = g >> 3, q = g & 7;
        O[base * 8 + g] = reinterpret_cast<const float4*>(so + p * SOW + q * 4)[0];
    }
}

// Tail kernel (only launched if n % 256 != 0; never for this problem's shapes).
__global__ void MVGeometricBilinear_41274635715139_tail(
    const float4* __restrict__ X, const float4* __restrict__ Y,
    const float* __restrict__ Rf, float4* __restrict__ O, int n0, int n)
{
    const int t = n0 + blockIdx.x * blockDim.x + threadIdx.x;
    if (t >= n) return;
    float x[16], y[16];
#pragma unroll
    for (int q = 0; q < 4; q++) {
        const float4 v = X[t * 4 + q];
        x[4 * q + 0] = v.x; x[4 * q + 1] = v.y; x[4 * q + 2] = v.z; x[4 * q + 3] = v.w;
        const float4 w = Y[t * 4 + q];
        y[4 * q + 0] = w.x; y[4 * q + 1] = w.y; y[4 * q + 2] = w.z; y[4 * q + 3] = w.w;
    }
    const float r = Rf[t * 16 + 15];
    float gp[16], jn[16];
    mv_compute(x, y, r, gp, jn);
    float4* o = O + t * 8;
#pragma unroll
    for (int q = 0; q < 4; q++) {
        o[q]     = make_float4(gp[4 * q], gp[4 * q + 1], gp[4 * q + 2], gp[4 * q + 3]);
        o[4 + q] = make_float4(jn[4 * q], jn[4 * q + 1], jn[4 * q + 2], jn[4 * q + 3]);
    }
}

extern "C" void kernel_launch(void* const* d_in, const int* in_sizes, int n_in,
                              void* d_out, int out_size)
{
    const float4* x = (const float4*)d_in[0];
    const float4* y = (const float4*)d_in[1];
    const float*  r = (const float*)d_in[2];
    float4* o = (float4*)d_out;

    const int n      = in_sizes[0] / 16;   // number of multivector points
    const int blocks = n / TPB;
    const int rem    = n - blocks * TPB;

    if (blocks > 0)
        MVGeometricBilinear_41274635715139_kernel<<<blocks, TPB>>>(x, y, r, o);
    if (rem > 0)
        MVGeometricBilinear_41274635715139_tail<<<(rem + 255) / 256, 256>>>(
            x, y, r, o, blocks * TPB, n);
}